// round 16
// baseline (speedup 1.0000x reference)
#include <cuda_runtime.h>
#include <cuda_fp16.h>
#include <cstdint>
#include <string.h>

typedef unsigned long long ull;
typedef unsigned int uint;

#define L    64
#define NGR  8192
#define HD   128
#define MM   32             // graphs per CTA
#define NTH  256            // 8 warps
#define AG   4

// ---- smem byte offsets ----
#define S_A    0            // A: 32 rows x 256 k fp16, SW128 blocked (16KB)
#define S_WB   16384        // per-warp B rings: 8 warps x 3 slots x 4KB = 96KB
#define S_TOT  114688       // 112KB -> 2 CTAs/SM

// W images: 8 = kc(4) x nh(2). Image = [256 n'][64 k'] fp16 SW128, 32KB.
// n' = n - 256*nh (gates 2nh, 2nh+1), k' = k - 64*kc.
__device__ __align__(128) unsigned char wblob[8 * 32768];
__device__ float bsum[512];                      // b_ih + b_hh
__device__ float hs_buf[(size_t)NGR * L * HD];   // 256MB hidden states

// ---- PTX helpers (base PTX; no tcgen05 on this toolchain) ----
__device__ __forceinline__ uint smem_u32(const void* p) {
    uint a; asm("{ .reg .u64 t; cvta.to.shared.u64 t, %1; cvt.u32.u64 %0, t; }"
                : "=r"(a) : "l"(p));
    return a;
}
#define CP_ASYNC16(dst, src) \
    asm volatile("cp.async.cg.shared.global [%0], [%1], 16;" :: "r"(dst), "l"(src))
#define CP_COMMIT() asm volatile("cp.async.commit_group;" ::: "memory")
#define CP_WAIT(n)  asm volatile("cp.async.wait_group %0;" :: "n"(n) : "memory")

__device__ __forceinline__ void ldmx4(uint* r, uint addr) {
    asm volatile("ldmatrix.sync.aligned.m8n8.x4.shared.b16 {%0,%1,%2,%3}, [%4];"
        : "=r"(r[0]), "=r"(r[1]), "=r"(r[2]), "=r"(r[3]) : "r"(addr));
}
__device__ __forceinline__ void mma16816(float* d, const uint* a, const uint* b) {
    asm volatile(
        "mma.sync.aligned.m16n8k16.row.col.f32.f16.f16.f32 "
        "{%0,%1,%2,%3}, {%4,%5,%6,%7}, {%8,%9}, {%0,%1,%2,%3};"
        : "+f"(d[0]), "+f"(d[1]), "+f"(d[2]), "+f"(d[3])
        : "r"(a[0]), "r"(a[1]), "r"(a[2]), "r"(a[3]), "r"(b[0]), "r"(b[1]));
}
// ---- MUFU activations ----
__device__ __forceinline__ float ex2a(float x) { float y; asm("ex2.approx.f32 %0, %1;" : "=f"(y) : "f"(x)); return y; }
__device__ __forceinline__ float rcpa(float x) { float y; asm("rcp.approx.f32 %0, %1;" : "=f"(y) : "f"(x)); return y; }
__device__ __forceinline__ float sigf(float x)  { return rcpa(1.0f + ex2a(-1.4426950408889634f * x)); }
__device__ __forceinline__ float tanhf_(float x){ return fmaf(2.0f, rcpa(1.0f + ex2a(-2.8853900817779268f * x)), -1.0f); }

__device__ __forceinline__ uint pk2h(float a, float b) {
    __half2 p = __floats2half2_rn(a, b);
    uint u; memcpy(&u, &p, 4); return u;
}
// A tile: 32 r x 256 k fp16; atoms 8r x 64k; atom = (r>>3) + (k>>6)*4 (16KB)
__device__ __forceinline__ uint a_off(int r, int k) {
    uint b = (uint)((((r >> 3) + (k >> 6) * 4) << 10) + ((r & 7) << 7) + ((k & 63) << 1));
    return b ^ ((b >> 3) & 0x70);
}
// W image: 256 n' x 64 k' fp16; atoms 8n x 64k (32KB)
__device__ __forceinline__ uint w_off(int n, int k) {
    uint b = (uint)(((n >> 3) << 10) + ((n & 7) << 7) + (k << 1));
    return b ^ ((b >> 3) & 0x70);
}

// ============ W prep: fp16 round into 8 [256n][64k] images + bsum ============
extern "C" __global__ void prep_kernel(const float* __restrict__ W_ih,
                                       const float* __restrict__ W_hh,
                                       const float* __restrict__ b_ih,
                                       const float* __restrict__ b_hh)
{
    int i = blockIdx.x * blockDim.x + threadIdx.x;   // 512*256
    if (i >= 512 * 256) return;
    int n = i >> 8, gk = i & 255;                    // gk: x 0..127, h 128..255
    float w = (gk < 128) ? W_ih[n * 128 + gk] : W_hh[n * 128 + (gk - 128)];
    int img = ((gk >> 6) << 1) + (n >> 8);           // kc*2 + nh
    *(__half*)(wblob + (size_t)img * 32768 + w_off(n & 255, gk & 63)) =
        __float2half_rn(w);
    if (i < 512) bsum[i] = b_ih[i] + b_hh[i];
}

// per-warp: copy this warp's 4KB slice (4 x 1KB atoms) of image `img`
// into its private ring slot. One commit group.
// q = g01*2 + nt; source atom = g01*16 + warp*2 + nt.
__device__ __forceinline__ void issue_slice(uint smb, int img, int slot,
                                            int warp, int lane)
{
    const int q = lane >> 3, l8 = lane & 7;          // q: atom 0..3
    const int atomIdx = ((q & 2) << 3) + warp * 2 + (q & 1);   // g01*16 + w*2 + nt
    const char* src = (const char*)wblob + (size_t)img * 32768
                    + atomIdx * 1024 + l8 * 128;
    uint dst = smb + S_WB + warp * 12288 + slot * 4096 + q * 1024 + l8 * 128;
    #pragma unroll
    for (int it = 0; it < 8; it++)
        CP_ASYNC16(dst + it * 16, src + it * 16);
    CP_COMMIT();
}

// ============ fused LSTM recurrence: per-warp B pipelines ============
extern "C" __global__ void __launch_bounds__(NTH, 2)
lstm_mma_kernel(const float* __restrict__ x)
{
    extern __shared__ __align__(1024) char sm[];
    const uint smb  = smem_u32(sm);
    const int tid   = threadIdx.x;
    const int lane  = tid & 31;
    const int warp  = tid >> 5;       // 0..7: 16 n-cols per gate
    const int graph0 = blockIdx.x * MM;

    // ldmatrix lane address components
    const int rA    = (lane & 7);
    const int mHalf = (lane >> 3) & 1;
    const uint aKsel = (uint)((lane >> 4) << 4);
    const uint aPre = (uint)(rA << 7);
    const uint swA  = (uint)(rA << 4);
    const uint bPre = (uint)((lane & 7) << 7);
    const uint swB  = (uint)((lane & 7) << 4);
    const uint bTile = (uint)((lane >> 3) << 4);
    const int jj   = (lane & 3) << 1;
    const int rowq = lane >> 2;
    const uint wring = smb + S_WB + warp * 12288;

    // zero h-region of A (k 128..255 = bytes [8192,16384))
    #pragma unroll
    for (int it = 0; it < 4; it++)
        ((ull*)(sm + S_A + 8192))[tid + it * NTH] = 0ull;

    float creg[2][2][4];               // [mt][nt][rg*2+cp]
    #pragma unroll
    for (int a = 0; a < 2; a++)
        #pragma unroll
        for (int b = 0; b < 2; b++)
            #pragma unroll
            for (int c = 0; c < 4; c++) creg[a][b][c] = 0.0f;

    // prime per-warp ring: slices of imgs 0,1,2 -> slots 0,1,2
    issue_slice(smb, 0, 0, warp, lane);
    issue_slice(smb, 1, 1, warp, lane);
    issue_slice(smb, 2, 2, warp, lane);
    int slot = 0;                      // = m % 3, m = global job index

    for (int t = 0; t < L; t++) {
        // stage x_t (writes A x-region; epilogue of t-1 wrote h-region;
        // both ordered vs MMAs by the sync below)
        #pragma unroll
        for (int it = 0; it < 4; it++) {
            int idx = tid + it * NTH;
            int g = idx >> 5, v = idx & 31;
            float4 xv = *(const float4*)(x + ((size_t)(graph0 + g) * L + t) * HD + v * 4);
            *(ull*)(sm + S_A + a_off(g, v * 4)) =
                (ull)pk2h(xv.x, xv.y) | ((ull)pk2h(xv.z, xv.w) << 32);
        }
        // acc seeded with bias
        float acc[2][4][2][4];         // [mt][gate][nt][frag]
        #pragma unroll
        for (int gt = 0; gt < 4; gt++)
            #pragma unroll
            for (int nt = 0; nt < 2; nt++) {
                float2 b = __ldg((const float2*)(bsum + gt * 128 + warp * 16 + nt * 8 + jj));
                #pragma unroll
                for (int mt = 0; mt < 2; mt++) {
                    acc[mt][gt][nt][0] = b.x; acc[mt][gt][nt][1] = b.y;
                    acc[mt][gt][nt][2] = b.x; acc[mt][gt][nt][3] = b.y;
                }
            }
        __syncthreads();               // S2: A complete -> MMAs may start

        // ---- 8 jobs, per-warp pipelined (NO block syncs inside) ----
        #pragma unroll
        for (int j = 0; j < 8; j++) {
            // wait for this warp's slice of img j (3-deep ring => allow 2 pending)
            if (t == L - 1 && j == 7)      { CP_WAIT(0); }
            else if (t == L - 1 && j == 6) { CP_WAIT(1); }
            else                           { CP_WAIT(2); }

            const int nh = j & 1, kc = j >> 1;
            const uint sb = wring + slot * 4096;

            #pragma unroll
            for (int k32 = 0; k32 < 2; k32++) {
                uint bfr[2][2][4];     // [g01][nt]
                const uint bLow = (uint)((k32 << 6) + bTile) ^ swB;
                #pragma unroll
                for (int g01 = 0; g01 < 2; g01++)
                    #pragma unroll
                    for (int nt = 0; nt < 2; nt++)
                        ldmx4(bfr[g01][nt],
                              sb + (uint)((g01 * 2 + nt) << 10) + bPre + bLow);
                #pragma unroll
                for (int k16 = 0; k16 < 2; k16++) {
                    const uint aLow = (uint)(((k32 * 2 + k16) << 5) + aKsel) ^ swA;
                    #pragma unroll
                    for (int mt = 0; mt < 2; mt++) {
                        uint ah[4];
                        ldmx4(ah, smb + S_A +
                              (uint)((2 * mt + mHalf + kc * 4) << 10) + aPre + aLow);
                        #pragma unroll
                        for (int g01 = 0; g01 < 2; g01++)
                            #pragma unroll
                            for (int nt = 0; nt < 2; nt++)
                                mma16816(acc[mt][2 * nh + g01][nt], ah,
                                         &bfr[g01][nt][k16 * 2]);
                    }
                }
            }
            // refill this slot with img (m+3): this warp's LDSMs for the slot
            // are in-order before these LDGSTS smem writes
            {
                int nm = t * 8 + j + 3;
                if (nm < 8 * L)
                    issue_slice(smb, nm & 7, slot, warp, lane);
            }
            slot = (slot == 2) ? 0 : slot + 1;
        }
        __syncthreads();               // S1: all warps' MMAs done -> A writable

        // ---- epilogue: lane-local LSTM update; h -> A fp16 + hs_buf fp32 ----
        #pragma unroll
        for (int mt = 0; mt < 2; mt++)
            #pragma unroll
            for (int rg = 0; rg < 2; rg++)
                #pragma unroll
                for (int nt = 0; nt < 2; nt++) {
                    float h2[2];
                    #pragma unroll
                    for (int cp = 0; cp < 2; cp++) {
                        const int fr = rg * 2 + cp;
                        float iv = sigf (acc[mt][0][nt][fr]);
                        float fv = sigf (acc[mt][1][nt][fr]);
                        float gv = tanhf_(acc[mt][2][nt][fr]);
                        float ov = sigf (acc[mt][3][nt][fr]);
                        float c  = fv * creg[mt][nt][fr] + iv * gv;
                        creg[mt][nt][fr] = c;
                        h2[cp] = ov * tanhf_(c);
                    }
                    const int g = mt * 16 + rg * 8 + rowq;
                    const int col0 = warp * 16 + nt * 8 + jj;
                    *(uint*)(sm + S_A + a_off(g, 128 + col0)) = pk2h(h2[0], h2[1]);
                    __stcs((float2*)(hs_buf + ((size_t)(graph0 + g) * L + t) * HD + col0),
                           make_float2(h2[0], h2[1]));
                }
        // next step's S2 orders epilogue + staging writes vs MMAs
    }
}

// ============ attention pooling: single pass over hs_buf ============
extern "C" __global__ void __launch_bounds__(256)
att_kernel(const float* __restrict__ W_att, const float* __restrict__ b_att,
           float* __restrict__ out)
{
    extern __shared__ float s[];
    float* Hs = s;                 // [4][64][128]
    float* Sc = s + 32768;         // [4][64]
    float* Pp = s + 33024;         // [8][128]
    const int tid = threadIdx.x, lane = tid & 31, warp = tid >> 5;
    const int graph0 = blockIdx.x * AG;
    const float batt = b_att[0];
    const float4 wa4 = *(const float4*)(W_att + lane * 4);

    #pragma unroll 4
    for (int it = 0; it < 32; it++) {
        const int g = it >> 3;
        const int t = (it & 7) * 8 + warp;
        float4 hv = __ldcs((const float4*)(hs_buf +
                        ((size_t)(graph0 + g) * L + t) * HD + lane * 4));
        *(float4*)(Hs + g * 8192 + t * 128 + lane * 4) = hv;
        float d = hv.x * wa4.x + hv.y * wa4.y + hv.z * wa4.z + hv.w * wa4.w;
        #pragma unroll
        for (int o = 16; o; o >>= 1)
            d += __shfl_xor_sync(0xffffffffu, d, o);
        if (lane == 0) Sc[g * 64 + t] = d + batt;
    }
    __syncthreads();

    if (warp < 4) {
        const int g = warp;
        float s1 = Sc[g * 64 + lane], s2 = Sc[g * 64 + 32 + lane];
        float m = fmaxf(s1, s2);
        #pragma unroll
        for (int o = 16; o; o >>= 1)
            m = fmaxf(m, __shfl_xor_sync(0xffffffffu, m, o));
        float e1 = ex2a(1.4426950408889634f * (s1 - m));
        float e2 = ex2a(1.4426950408889634f * (s2 - m));
        float z = e1 + e2;
        #pragma unroll
        for (int o = 16; o; o >>= 1)
            z += __shfl_xor_sync(0xffffffffu, z, o);
        float inv = rcpa(z);
        Sc[g * 64 + lane] = e1 * inv;
        Sc[g * 64 + 32 + lane] = e2 * inv;
    }
    __syncthreads();

    {
        const int g = warp >> 1;
        float4 a4 = make_float4(0.f, 0.f, 0.f, 0.f);
        #pragma unroll 4
        for (int tt = 0; tt < 32; tt++) {
            const int t = (warp & 1) * 32 + tt;
            float wt = Sc[g * 64 + t];
            float4 hv = *(const float4*)(Hs + g * 8192 + t * 128 + lane * 4);
            a4.x = fmaf(wt, hv.x, a4.x);
            a4.y = fmaf(wt, hv.y, a4.y);
            a4.z = fmaf(wt, hv.z, a4.z);
            a4.w = fmaf(wt, hv.w, a4.w);
        }
        *(float4*)(Pp + warp * 128 + lane * 4) = a4;
    }
    __syncthreads();

    {
        const int g = tid >> 6, q = tid & 63;
        float v0 = Pp[(2 * g) * 128 + 2 * q]     + Pp[(2 * g + 1) * 128 + 2 * q];
        float v1 = Pp[(2 * g) * 128 + 2 * q + 1] + Pp[(2 * g + 1) * 128 + 2 * q + 1];
        *(float2*)(out + (size_t)(graph0 + g) * HD + 2 * q) = make_float2(v0, v1);
    }
}

extern "C" void kernel_launch(void* const* d_in, const int* in_sizes, int n_in,
                              void* d_out, int out_size)
{
    const float* x     = (const float*)d_in[0];
    // d_in[1] = batch (arange(N)//L), unused
    const float* W_ih  = (const float*)d_in[2];
    const float* W_hh  = (const float*)d_in[3];
    const float* b_ih  = (const float*)d_in[4];
    const float* b_hh  = (const float*)d_in[5];
    const float* W_att = (const float*)d_in[6];
    const float* b_att = (const float*)d_in[7];
    float* out = (float*)d_out;

    prep_kernel<<<512, 256>>>(W_ih, W_hh, b_ih, b_hh);
    cudaFuncSetAttribute(lstm_mma_kernel,
                         cudaFuncAttributeMaxDynamicSharedMemorySize, S_TOT);
    lstm_mma_kernel<<<NGR / MM, NTH, S_TOT>>>(x);
    const int att_smem = (32768 + 256 + 1024) * 4;
    cudaFuncSetAttribute(att_kernel,
                         cudaFuncAttributeMaxDynamicSharedMemorySize, att_smem);
    att_kernel<<<NGR / AG, 256, att_smem>>>(W_att, b_att, out);
}

// round 17
// speedup vs baseline: 1.7936x; 1.7936x over previous
#include <cuda_runtime.h>
#include <cuda_fp16.h>
#include <cstdint>
#include <string.h>

typedef unsigned long long ull;
typedef unsigned int uint;

#define L    64
#define NGR  8192
#define HD   128
#define MM   64             // graphs per CTA
#define NTH  512            // 16 warps
#define AG   4

// ---- smem byte offsets ----
#define S_A    0            // A: 64 rows x 256 k fp16, SW128 blocked (32KB)
#define S_W0   32768        // resident images 0..3 (4 x 32KB = 128KB)
#define S_WB   163840       // stream ring: 2 x 32KB
#define S_TOT  229376       // 224KB -> 1 CTA/SM

// W images: 8 = kc(4) x nh(2). Image = [256 n'][64 k'] fp16 SW128, 32KB.
// n' = n - 256*nh (gates 2nh, 2nh+1), k' = k - 64*kc.
__device__ __align__(128) unsigned char wblob[8 * 32768];
__device__ float bsum[512];                      // b_ih + b_hh
__device__ float hs_buf[(size_t)NGR * L * HD];   // 256MB hidden states

// ---- PTX helpers (base PTX; no tcgen05 on this toolchain) ----
__device__ __forceinline__ uint smem_u32(const void* p) {
    uint a; asm("{ .reg .u64 t; cvta.to.shared.u64 t, %1; cvt.u32.u64 %0, t; }"
                : "=r"(a) : "l"(p));
    return a;
}
#define CP_ASYNC16(dst, src) \
    asm volatile("cp.async.cg.shared.global [%0], [%1], 16;" :: "r"(dst), "l"(src))
#define CP_COMMIT() asm volatile("cp.async.commit_group;" ::: "memory")
#define CP_WAIT(n)  asm volatile("cp.async.wait_group %0;" :: "n"(n) : "memory")

__device__ __forceinline__ void ldmx4(uint* r, uint addr) {
    asm volatile("ldmatrix.sync.aligned.m8n8.x4.shared.b16 {%0,%1,%2,%3}, [%4];"
        : "=r"(r[0]), "=r"(r[1]), "=r"(r[2]), "=r"(r[3]) : "r"(addr));
}
__device__ __forceinline__ void mma16816(float* d, const uint* a, const uint* b) {
    asm volatile(
        "mma.sync.aligned.m16n8k16.row.col.f32.f16.f16.f32 "
        "{%0,%1,%2,%3}, {%4,%5,%6,%7}, {%8,%9}, {%0,%1,%2,%3};"
        : "+f"(d[0]), "+f"(d[1]), "+f"(d[2]), "+f"(d[3])
        : "r"(a[0]), "r"(a[1]), "r"(a[2]), "r"(a[3]), "r"(b[0]), "r"(b[1]));
}
// ---- MUFU activations ----
__device__ __forceinline__ float ex2a(float x) { float y; asm("ex2.approx.f32 %0, %1;" : "=f"(y) : "f"(x)); return y; }
__device__ __forceinline__ float rcpa(float x) { float y; asm("rcp.approx.f32 %0, %1;" : "=f"(y) : "f"(x)); return y; }
__device__ __forceinline__ float sigf(float x)  { return rcpa(1.0f + ex2a(-1.4426950408889634f * x)); }
__device__ __forceinline__ float tanhf_(float x){ return fmaf(2.0f, rcpa(1.0f + ex2a(-2.8853900817779268f * x)), -1.0f); }

__device__ __forceinline__ uint pk2h(float a, float b) {
    __half2 p = __floats2half2_rn(a, b);
    uint u; memcpy(&u, &p, 4); return u;
}
// A tile: 64 r x 256 k fp16; atoms 8r x 64k; atom = (r>>3) + (k>>6)*8 (32KB)
__device__ __forceinline__ uint a_off(int r, int k) {
    uint b = (uint)((((r >> 3) + (k >> 6) * 8) << 10) + ((r & 7) << 7) + ((k & 63) << 1));
    return b ^ ((b >> 3) & 0x70);
}
// W image: 256 n' x 64 k' fp16; atoms 8n x 64k (32KB)
__device__ __forceinline__ uint w_off(int n, int k) {
    uint b = (uint)(((n >> 3) << 10) + ((n & 7) << 7) + (k << 1));
    return b ^ ((b >> 3) & 0x70);
}

// ============ W prep: fp16 round into 8 [256n][64k] images + bsum ============
extern "C" __global__ void prep_kernel(const float* __restrict__ W_ih,
                                       const float* __restrict__ W_hh,
                                       const float* __restrict__ b_ih,
                                       const float* __restrict__ b_hh)
{
    int i = blockIdx.x * blockDim.x + threadIdx.x;   // 512*256
    if (i >= 512 * 256) return;
    int n = i >> 8, gk = i & 255;                    // gk: x 0..127, h 128..255
    float w = (gk < 128) ? W_ih[n * 128 + gk] : W_hh[n * 128 + (gk - 128)];
    int img = ((gk >> 6) << 1) + (n >> 8);           // kc*2 + nh
    *(__half*)(wblob + (size_t)img * 32768 + w_off(n & 255, gk & 63)) =
        __float2half_rn(w);
    if (i < 512) bsum[i] = b_ih[i] + b_hh[i];
}

// block-wide: copy one 32KB image to smem dst (64B/thread), one commit group
__device__ __forceinline__ void issue_img(uint dstBase, int img, int tid) {
    const char* src = (const char*)wblob + (size_t)img * 32768 + tid * 16;
    uint dst = dstBase + tid * 16;
    #pragma unroll
    for (int it = 0; it < 4; it++)
        CP_ASYNC16(dst + it * 8192, src + it * 8192);
    CP_COMMIT();
}

// ============ fused LSTM recurrence: MM=64, resident half-W ============
extern "C" __global__ void __launch_bounds__(NTH, 1)
lstm_mma_kernel(const float* __restrict__ x)
{
    extern __shared__ __align__(1024) char sm[];
    const uint smb  = smem_u32(sm);
    const int tid   = threadIdx.x;
    const int lane  = tid & 31;
    const int warp  = tid >> 5;       // 0..15: 8 n-cols per gate
    const int graph0 = blockIdx.x * MM;

    // ldmatrix lane address components
    const int rA    = (lane & 7);
    const int mHalf = (lane >> 3) & 1;
    const uint aKsel = (uint)((lane >> 4) << 4);
    const uint aPre = (uint)(rA << 7);
    const uint swA  = (uint)(rA << 4);
    const uint bPre = (uint)((lane & 7) << 7);
    const uint swB  = (uint)((lane & 7) << 4);
    const uint bTile = (uint)((lane >> 3) << 4);
    const int jj   = (lane & 3) << 1;
    const int rowq = lane >> 2;

    // bias seeds (per gate, this warp's col pair)
    float bseed[4][2];
    #pragma unroll
    for (int gt = 0; gt < 4; gt++) {
        float2 b = *(const float2*)(bsum + gt * 128 + warp * 8 + jj);
        bseed[gt][0] = b.x; bseed[gt][1] = b.y;
    }

    // prologue: resident images 0..3
    issue_img(smb + S_W0,          0, tid);
    issue_img(smb + S_W0 + 32768,  1, tid);
    issue_img(smb + S_W0 + 65536,  2, tid);
    issue_img(smb + S_W0 + 98304,  3, tid);
    // zero h-region of A (k 128..255 = bytes [16384,32768))
    #pragma unroll
    for (int it = 0; it < 4; it++)
        ((ull*)(sm + S_A + 16384))[tid + it * NTH] = 0ull;

    float creg[4][4];
    #pragma unroll
    for (int a = 0; a < 4; a++)
        #pragma unroll
        for (int b = 0; b < 4; b++) creg[a][b] = 0.0f;

    CP_WAIT(0);
    __syncthreads();   // resident W + A h-zero visible

    for (int t = 0; t < L; t++) {
        // stage x_t: 64 graphs x 128 fp32 -> A k[0..127] fp16
        #pragma unroll
        for (int it = 0; it < 4; it++) {
            int idx = tid + it * NTH;
            int g = idx >> 5, v = idx & 31;
            float4 xv = *(const float4*)(x + ((size_t)(graph0 + g) * L + t) * HD + v * 4);
            *(ull*)(sm + S_A + a_off(g, v * 4)) =
                (ull)pk2h(xv.x, xv.y) | ((ull)pk2h(xv.z, xv.w) << 32);
        }
        // acc seeded with bias
        float acc[4][4][4];            // [mt][gate][frag]
        #pragma unroll
        for (int mt = 0; mt < 4; mt++)
            #pragma unroll
            for (int gt = 0; gt < 4; gt++) {
                acc[mt][gt][0] = bseed[gt][0]; acc[mt][gt][1] = bseed[gt][1];
                acc[mt][gt][2] = bseed[gt][0]; acc[mt][gt][3] = bseed[gt][1];
            }
        __syncthreads();               // S2: A complete -> MMAs may start

        // issue streamed imgs 4,5 (consumed after resident jobs 0-3)
        issue_img(smb + S_WB,         4, tid);
        issue_img(smb + S_WB + 32768, 5, tid);

        // ---- 8 jobs: 0-3 resident, 4-7 streamed ----
        #pragma unroll
        for (int j = 0; j < 8; j++) {
            uint wb;
            if (j < 4) {
                wb = smb + S_W0 + j * 32768;               // resident, no wait
            } else if (j == 4) {
                CP_WAIT(1); __syncthreads();               // img4 visible
                wb = smb + S_WB;
            } else if (j == 5) {
                CP_WAIT(0); __syncthreads();               // img5 visible; job4 done
                issue_img(smb + S_WB, 6, tid);             // refill slot0
                wb = smb + S_WB + 32768;
            } else if (j == 6) {
                CP_WAIT(0); __syncthreads();               // img6 visible; job5 done
                issue_img(smb + S_WB + 32768, 7, tid);     // refill slot1
                wb = smb + S_WB;
            } else {
                CP_WAIT(0); __syncthreads();               // img7 visible; job6 done
                wb = smb + S_WB + 32768;
            }
            const int nh = j & 1, kc = j >> 1;

            #pragma unroll
            for (int k32 = 0; k32 < 2; k32++) {
                uint bfr[2][4];        // [g01] -> 2 k16 x 2 regs
                const uint bLow = (uint)((k32 << 6) + bTile) ^ swB;
                #pragma unroll
                for (int g01 = 0; g01 < 2; g01++)
                    ldmx4(bfr[g01],
                          wb + (uint)((g01 * 16 + warp) << 10) + bPre + bLow);
                #pragma unroll
                for (int k16 = 0; k16 < 2; k16++) {
                    const uint aLow = (uint)(((k32 * 2 + k16) << 5) + aKsel) ^ swA;
                    #pragma unroll
                    for (int mt = 0; mt < 4; mt++) {
                        uint ah[4];
                        ldmx4(ah, smb + S_A +
                              (uint)((2 * mt + mHalf + kc * 8) << 10) + aPre + aLow);
                        #pragma unroll
                        for (int g01 = 0; g01 < 2; g01++)
                            mma16816(acc[mt][2 * nh + g01], ah,
                                     &bfr[g01][k16 * 2]);
                    }
                }
            }
        }
        __syncthreads();               // S1: all MMAs done -> A writable

        // ---- epilogue: lane-local LSTM update; h -> A fp16 + hs_buf fp32 ----
        #pragma unroll
        for (int mt = 0; mt < 4; mt++)
            #pragma unroll
            for (int rg = 0; rg < 2; rg++) {
                float h2[2];
                #pragma unroll
                for (int cp = 0; cp < 2; cp++) {
                    const int fr = rg * 2 + cp;
                    float iv = sigf (acc[mt][0][fr]);
                    float fv = sigf (acc[mt][1][fr]);
                    float gv = tanhf_(acc[mt][2][fr]);
                    float ov = sigf (acc[mt][3][fr]);
                    float c  = fv * creg[mt][fr] + iv * gv;
                    creg[mt][fr] = c;
                    h2[cp] = ov * tanhf_(c);
                }
                const int g = mt * 16 + rg * 8 + rowq;
                const int col0 = warp * 8 + jj;
                *(uint*)(sm + S_A + a_off(g, 128 + col0)) = pk2h(h2[0], h2[1]);
                __stcs((float2*)(hs_buf + ((size_t)(graph0 + g) * L + t) * HD + col0),
                       make_float2(h2[0], h2[1]));
            }
        // next step's S2 orders epilogue + staging writes vs MMAs
    }
}

// ============ attention pooling: single pass over hs_buf ============
extern "C" __global__ void __launch_bounds__(256)
att_kernel(const float* __restrict__ W_att, const float* __restrict__ b_att,
           float* __restrict__ out)
{
    extern __shared__ float s[];
    float* Hs = s;                 // [4][64][128]
    float* Sc = s + 32768;         // [4][64]
    float* Pp = s + 33024;         // [8][128]
    const int tid = threadIdx.x, lane = tid & 31, warp = tid >> 5;
    const int graph0 = blockIdx.x * AG;
    const float batt = b_att[0];
    const float4 wa4 = *(const float4*)(W_att + lane * 4);

    #pragma unroll 4
    for (int it = 0; it < 32; it++) {
        const int g = it >> 3;
        const int t = (it & 7) * 8 + warp;
        float4 hv = __ldcs((const float4*)(hs_buf +
                        ((size_t)(graph0 + g) * L + t) * HD + lane * 4));
        *(float4*)(Hs + g * 8192 + t * 128 + lane * 4) = hv;
        float d = hv.x * wa4.x + hv.y * wa4.y + hv.z * wa4.z + hv.w * wa4.w;
        #pragma unroll
        for (int o = 16; o; o >>= 1)
            d += __shfl_xor_sync(0xffffffffu, d, o);
        if (lane == 0) Sc[g * 64 + t] = d + batt;
    }
    __syncthreads();

    if (warp < 4) {
        const int g = warp;
        float s1 = Sc[g * 64 + lane], s2 = Sc[g * 64 + 32 + lane];
        float m = fmaxf(s1, s2);
        #pragma unroll
        for (int o = 16; o; o >>= 1)
            m = fmaxf(m, __shfl_xor_sync(0xffffffffu, m, o));
        float e1 = ex2a(1.4426950408889634f * (s1 - m));
        float e2 = ex2a(1.4426950408889634f * (s2 - m));
        float z = e1 + e2;
        #pragma unroll
        for (int o = 16; o; o >>= 1)
            z += __shfl_xor_sync(0xffffffffu, z, o);
        float inv = rcpa(z);
        Sc[g * 64 + lane] = e1 * inv;
        Sc[g * 64 + 32 + lane] = e2 * inv;
    }
    __syncthreads();

    {
        const int g = warp >> 1;
        float4 a4 = make_float4(0.f, 0.f, 0.f, 0.f);
        #pragma unroll 4
        for (int tt = 0; tt < 32; tt++) {
            const int t = (warp & 1) * 32 + tt;
            float wt = Sc[g * 64 + t];
            float4 hv = *(const float4*)(Hs + g * 8192 + t * 128 + lane * 4);
            a4.x = fmaf(wt, hv.x, a4.x);
            a4.y = fmaf(wt, hv.y, a4.y);
            a4.z = fmaf(wt, hv.z, a4.z);
            a4.w = fmaf(wt, hv.w, a4.w);
        }
        *(float4*)(Pp + warp * 128 + lane * 4) = a4;
    }
    __syncthreads();

    {
        const int g = tid >> 6, q = tid & 63;
        float v0 = Pp[(2 * g) * 128 + 2 * q]     + Pp[(2 * g + 1) * 128 + 2 * q];
        float v1 = Pp[(2 * g) * 128 + 2 * q + 1] + Pp[(2 * g + 1) * 128 + 2 * q + 1];
        *(float2*)(out + (size_t)(graph0 + g) * HD + 2 * q) = make_float2(v0, v1);
    }
}

extern "C" void kernel_launch(void* const* d_in, const int* in_sizes, int n_in,
                              void* d_out, int out_size)
{
    const float* x     = (const float*)d_in[0];
    // d_in[1] = batch (arange(N)//L), unused
    const float* W_ih  = (const float*)d_in[2];
    const float* W_hh  = (const float*)d_in[3];
    const float* b_ih  = (const float*)d_in[4];
    const float* b_hh  = (const float*)d_in[5];
    const float* W_att = (const float*)d_in[6];
    const float* b_att = (const float*)d_in[7];
    float* out = (float*)d_out;

    prep_kernel<<<512, 256>>>(W_ih, W_hh, b_ih, b_hh);
    cudaFuncSetAttribute(lstm_mma_kernel,
                         cudaFuncAttributeMaxDynamicSharedMemorySize, S_TOT);
    lstm_mma_kernel<<<NGR / MM, NTH, S_TOT>>>(x);
    const int att_smem = (32768 + 256 + 1024) * 4;
    cudaFuncSetAttribute(att_kernel,
                         cudaFuncAttributeMaxDynamicSharedMemorySize, att_smem);
    att_kernel<<<NGR / AG, 256, att_smem>>>(W_att, b_att, out);
}